// round 5
// baseline (speedup 1.0000x reference)
#include <cuda_runtime.h>
#include <cstdint>

// Problem constants (match reference_code)
#define T_SZ 1000000u
#define G_SZ 500000u
#define K_SZ 9u
#define GK      (G_SZ * K_SZ)      // 4,500,000 slots per batch
#define NGROUPS (GK / 4u)          // 1,125,000 int4 index groups
#define TPL     (NGROUPS / 4u)     // 281,250 threads per launch (4 groups each)
#define NPASS   4u
#define TREG    (T_SZ / NPASS)     // 250,000 texels per region = 16MB

// One 64B texel row: gather (nc) + streaming store (cs, evict-first).
__device__ __forceinline__ void copy_slot(const char* __restrict__ src,
                                          char* __restrict__ dst) {
    unsigned long long a[4], b[4];
    asm("ld.global.nc.v4.b64 {%0,%1,%2,%3}, [%4];"
        : "=l"(a[0]), "=l"(a[1]), "=l"(a[2]), "=l"(a[3]) : "l"(src));
    asm("ld.global.nc.v4.b64 {%0,%1,%2,%3}, [%4];"
        : "=l"(b[0]), "=l"(b[1]), "=l"(b[2]), "=l"(b[3]) : "l"(src + 32));
    asm volatile("st.global.cs.v4.b64 [%0], {%1,%2,%3,%4};"
                 :: "l"(dst), "l"(a[0]), "l"(a[1]), "l"(a[2]), "l"(a[3]) : "memory");
    asm volatile("st.global.cs.v4.b64 [%0], {%1,%2,%3,%4};"
                 :: "l"(dst + 32), "l"(b[0]), "l"(b[1]), "l"(b[2]), "l"(b[3]) : "memory");
}

__device__ __forceinline__ void do_slot(int t, unsigned slot, unsigned tlo,
                                        const char* __restrict__ tex_b,
                                        char* __restrict__ out_b) {
    // active iff t in [tlo, tlo + TREG)
    if ((unsigned)t - tlo < TREG) {
        copy_slot(tex_b + (size_t)(unsigned)t * 64u,
                  out_b + (size_t)slot * 64u);
    }
}

// One (batch, region) pass: re-scan all indices, gather only those whose
// texel falls in [tlo, tlo+TREG). Working set = 16MB -> L2-resident by
// construction; texture DRAM reads collapse to compulsory misses.
__global__ __launch_bounds__(256) void gather_pass_kernel(
    const char* __restrict__ tex_b,   // this batch's texture [T,16] f32
    const int*  __restrict__ gidx,    // [G*K]
    char*       __restrict__ out_b,   // this batch's output [G,K,16] f32
    unsigned tlo)                     // region lower bound
{
    const unsigned tid = blockIdx.x * 256u + threadIdx.x;
    if (tid >= TPL) return;

    // 4 independent, fully-coalesced int4 index loads (16 slots)
    const int4* g4 = (const int4*)gidx;
    const int4 i0 = __ldg(&g4[tid]);
    const int4 i1 = __ldg(&g4[tid +      TPL]);
    const int4 i2 = __ldg(&g4[tid + 2u * TPL]);
    const int4 i3 = __ldg(&g4[tid + 3u * TPL]);

    const unsigned s0 = tid * 4u;
    const unsigned s1 = (tid +      TPL) * 4u;
    const unsigned s2 = (tid + 2u * TPL) * 4u;
    const unsigned s3 = (tid + 3u * TPL) * 4u;

    do_slot(i0.x, s0 + 0u, tlo, tex_b, out_b);
    do_slot(i0.y, s0 + 1u, tlo, tex_b, out_b);
    do_slot(i0.z, s0 + 2u, tlo, tex_b, out_b);
    do_slot(i0.w, s0 + 3u, tlo, tex_b, out_b);

    do_slot(i1.x, s1 + 0u, tlo, tex_b, out_b);
    do_slot(i1.y, s1 + 1u, tlo, tex_b, out_b);
    do_slot(i1.z, s1 + 2u, tlo, tex_b, out_b);
    do_slot(i1.w, s1 + 3u, tlo, tex_b, out_b);

    do_slot(i2.x, s2 + 0u, tlo, tex_b, out_b);
    do_slot(i2.y, s2 + 1u, tlo, tex_b, out_b);
    do_slot(i2.z, s2 + 2u, tlo, tex_b, out_b);
    do_slot(i2.w, s2 + 3u, tlo, tex_b, out_b);

    do_slot(i3.x, s3 + 0u, tlo, tex_b, out_b);
    do_slot(i3.y, s3 + 1u, tlo, tex_b, out_b);
    do_slot(i3.z, s3 + 2u, tlo, tex_b, out_b);
    do_slot(i3.w, s3 + 3u, tlo, tex_b, out_b);
}

extern "C" void kernel_launch(void* const* d_in, const int* in_sizes, int n_in,
                              void* d_out, int out_size) {
    // metadata order: [0] mesh_ids (unused), [1] textures f32 [B,T,C], [2] group_idx i32 [G,K]
    const char* tex  = (const char*)d_in[1];
    const int*  gidx = (const int*)d_in[2];
    char*       out  = (char*)d_out;

    const unsigned blocks = (TPL + 255u) / 256u;   // 1099
    // 8 serialized passes: batch-major, region-major within batch.
    for (unsigned b = 0; b < 2u; b++) {
        const char* tex_b = tex + (size_t)b * ((size_t)T_SZ * 64u);
        char*       out_b = out + (size_t)b * ((size_t)GK * 64u);
        for (unsigned p = 0; p < NPASS; p++) {
            gather_pass_kernel<<<blocks, 256>>>(tex_b, gidx, out_b, p * TREG);
        }
    }
}

// round 6
// speedup vs baseline: 1.1881x; 1.1881x over previous
#include <cuda_runtime.h>
#include <cstdint>

// Problem constants (match reference_code)
#define T_SZ 1000000u
#define G_SZ 500000u
#define K_SZ 9u
#define GK     (G_SZ * K_SZ)       // 4,500,000 slots per batch
#define EIGHTH (GK / 8u)           // 562,500
#define TPL    (EIGHTH * 2u)       // 1,125,000 threads per pass (c8 split)
#define NREG   2u
#define TREG   (T_SZ / NREG)       // 500,000 texels per region = 32MB

// 32B non-coherent gather
__device__ __forceinline__ void ldg_32B(const void* p, unsigned long long r[4]) {
    asm("ld.global.nc.v4.b64 {%0,%1,%2,%3}, [%4];"
        : "=l"(r[0]), "=l"(r[1]), "=l"(r[2]), "=l"(r[3]) : "l"(p));
}
// 32B streaming store (evict-first)
__device__ __forceinline__ void stg_cs_32B(void* p, const unsigned long long r[4]) {
    asm volatile("st.global.cs.v4.b64 [%0], {%1,%2,%3,%4};"
                 :: "l"(p), "l"(r[0]), "l"(r[1]), "l"(r[2]), "l"(r[3]) : "memory");
}

// One (batch, region) pass. Coalesced layout: thread i -> c8 = i&1 (which 32B
// half of the 64B slot), q = i>>1; lane pairs cover a slot, consecutive lanes
// cover consecutive slots -> stores merge across lanes. Each thread serves
// 8 slots (q + j*EIGHTH); at 50% region activity that's ~4 independent
// gathers in flight. Texture working set per pass = 32MB -> L2-resident.
__global__ __launch_bounds__(256) void gather_pass_kernel(
    const char* __restrict__ tex_b,   // this batch's texture [T,16] f32
    const int*  __restrict__ gidx,    // [G*K]
    char*       __restrict__ out_b,   // this batch's output [G,K,16] f32
    unsigned tlo)                     // region lower bound
{
    const unsigned i = blockIdx.x * 256u + threadIdx.x;
    if (i >= TPL) return;

    const unsigned c8 = (i & 1u) * 32u;   // byte offset within the 64B slot
    const unsigned q  = i >> 1;           // [0, EIGHTH)

    // 8 index loads (lane pairs share one idx -> broadcast; coalesced per j)
    unsigned t[8];
#pragma unroll
    for (int j = 0; j < 8; j++)
        t[j] = (unsigned)__ldg(&gidx[q + (unsigned)j * EIGHTH]);

    bool act[8];
#pragma unroll
    for (int j = 0; j < 8; j++)
        act[j] = (t[j] - tlo) < TREG;

    // Group 1: slots 0..3 — batch the 4 predicated loads, then 4 stores.
    {
        unsigned long long v[4][4];
#pragma unroll
        for (int j = 0; j < 4; j++)
            if (act[j]) ldg_32B(tex_b + (size_t)t[j] * 64u + c8, v[j]);
#pragma unroll
        for (int j = 0; j < 4; j++)
            if (act[j]) stg_cs_32B(out_b + (size_t)(q + (unsigned)j * EIGHTH) * 64u + c8, v[j]);
    }
    // Group 2: slots 4..7
    {
        unsigned long long v[4][4];
#pragma unroll
        for (int j = 4; j < 8; j++)
            if (act[j]) ldg_32B(tex_b + (size_t)t[j] * 64u + c8, v[j - 4]);
#pragma unroll
        for (int j = 4; j < 8; j++)
            if (act[j]) stg_cs_32B(out_b + (size_t)(q + (unsigned)j * EIGHTH) * 64u + c8, v[j - 4]);
    }
}

extern "C" void kernel_launch(void* const* d_in, const int* in_sizes, int n_in,
                              void* d_out, int out_size) {
    // metadata order: [0] mesh_ids (unused), [1] textures f32 [B,T,C], [2] group_idx i32 [G,K]
    const char* tex  = (const char*)d_in[1];
    const int*  gidx = (const int*)d_in[2];
    char*       out  = (char*)d_out;

    const unsigned blocks = (TPL + 255u) / 256u;   // 4395
    // 4 serialized passes: batch-major, region-major within batch.
    for (unsigned b = 0; b < 2u; b++) {
        const char* tex_b = tex + (size_t)b * ((size_t)T_SZ * 64u);
        char*       out_b = out + (size_t)b * ((size_t)GK * 64u);
        for (unsigned p = 0; p < NREG; p++) {
            gather_pass_kernel<<<blocks, 256>>>(tex_b, gidx, out_b, p * TREG);
        }
    }
}

// round 8
// speedup vs baseline: 1.3007x; 1.0947x over previous
#include <cuda_runtime.h>
#include <cstdint>

// Problem constants (match reference_code)
#define T_SZ 1000000u
#define G_SZ 500000u
#define K_SZ 9u
#define GK    (G_SZ * K_SZ)      // 4,500,000 slots per batch
#define QTR   (GK / 4u)          // 1,125,000 slots per quarter
#define TPP   (QTR * 2u)         // 2,250,000 threads per phase (c8 split)
#define NREG  2u
#define TREG  (T_SZ / NREG)      // 500,000 texels per region = 32MB

// 32B non-coherent gather
__device__ __forceinline__ void ldg_32B(const void* p, unsigned long long r[4]) {
    asm("ld.global.nc.v4.b64 {%0,%1,%2,%3}, [%4];"
        : "=l"(r[0]), "=l"(r[1]), "=l"(r[2]), "=l"(r[3]) : "l"(p));
}
// 32B streaming store (evict-first: keep output writes out of L2)
__device__ __forceinline__ void stg_cs_32B(void* p, const unsigned long long r[4]) {
    asm volatile("st.global.cs.v4.b64 [%0], {%1,%2,%3,%4};"
                 :: "l"(p), "l"(r[0]), "l"(r[1]), "l"(r[2]), "l"(r[3]) : "memory");
}

// Single-launch region-phased gather.
// Grid is 4 phases of bpp blocks: phase = (batch<<1)|region, scheduled in
// increasing blockIdx order -> blocks of one phase run as a temporal wave,
// so the gather working set per phase is one 32MB texture region (L2-resident
// by construction; L2 = 126MB).
// Thread layout (per phase, R4-proven): i -> c8 = i&1 (32B half of the 64B
// slot), q = i>>1; each thread serves 4 slots q + j*QTR. Slots whose texel
// falls outside this phase's region are skipped (the sibling region phase
// writes them). Pair-wise load/store keeps live registers low (occ fix vs R6).
__global__ __launch_bounds__(256) void gather_phased_kernel(
    const char* __restrict__ tex,    // [B,T,16] f32 (64B per texel row)
    const int*  __restrict__ gidx,   // [G*K]
    char*       __restrict__ out,    // [B,G,K,16] f32 (64B per slot)
    unsigned bpp)                    // blocks per phase
{
    const unsigned phase = blockIdx.x / bpp;            // 0..3
    const unsigned b     = phase >> 1;                  // batch-major outer
    const unsigned tlo   = (phase & 1u) * TREG;         // region lower bound
    const unsigned i     = (blockIdx.x - phase * bpp) * 256u + threadIdx.x;
    if (i >= TPP) return;

    const unsigned c8 = (i & 1u) * 32u;
    const unsigned q  = i >> 1;                         // [0, QTR)

    const char* tb = tex + (size_t)b * ((size_t)T_SZ * 64u);
    char*       ob = out + (size_t)b * ((size_t)GK * 64u);

    // 4 coalesced index loads (lane pairs broadcast-share each idx)
    const unsigned t0 = (unsigned)__ldg(&gidx[q]);
    const unsigned t1 = (unsigned)__ldg(&gidx[q +      QTR]);
    const unsigned t2 = (unsigned)__ldg(&gidx[q + 2u * QTR]);
    const unsigned t3 = (unsigned)__ldg(&gidx[q + 3u * QTR]);

    const bool a0 = (t0 - tlo) < TREG;
    const bool a1 = (t1 - tlo) < TREG;
    const bool a2 = (t2 - tlo) < TREG;
    const bool a3 = (t3 - tlo) < TREG;

    // Pair 1: slots 0,1 — two predicated gathers in flight, then two stores.
    {
        unsigned long long v0[4], v1[4];
        if (a0) ldg_32B(tb + (size_t)t0 * 64u + c8, v0);
        if (a1) ldg_32B(tb + (size_t)t1 * 64u + c8, v1);
        if (a0) stg_cs_32B(ob + (size_t)q * 64u + c8, v0);
        if (a1) stg_cs_32B(ob + (size_t)(q + QTR) * 64u + c8, v1);
    }
    // Pair 2: slots 2,3
    {
        unsigned long long v2[4], v3[4];
        if (a2) ldg_32B(tb + (size_t)t2 * 64u + c8, v2);
        if (a3) ldg_32B(tb + (size_t)t3 * 64u + c8, v3);
        if (a2) stg_cs_32B(ob + (size_t)(q + 2u * QTR) * 64u + c8, v2);
        if (a3) stg_cs_32B(ob + (size_t)(q + 3u * QTR) * 64u + c8, v3);
    }
}

extern "C" void kernel_launch(void* const* d_in, const int* in_sizes, int n_in,
                              void* d_out, int out_size) {
    // metadata order: [0] mesh_ids (unused), [1] textures f32 [B,T,C], [2] group_idx i32 [G,K]
    const char* tex  = (const char*)d_in[1];
    const int*  gidx = (const int*)d_in[2];
    char*       out  = (char*)d_out;

    const unsigned bpp    = (TPP + 255u) / 256u;  // 8790 blocks per phase
    const unsigned blocks = bpp * 4u;             // 35,160 (2 batches x 2 regions)
    gather_phased_kernel<<<blocks, 256>>>(tex, gidx, out, bpp);
}

// round 9
// speedup vs baseline: 1.3937x; 1.0715x over previous
#include <cuda_runtime.h>
#include <cstdint>

// Problem constants (match reference_code)
#define T_SZ 1000000u
#define G_SZ 500000u
#define K_SZ 9u
#define GK    (G_SZ * K_SZ)      // 4,500,000 slots per batch
#define QTR   (GK / 4u)          // 1,125,000 slots per quarter
#define TPP   (QTR * 2u)         // 2,250,000 threads per phase (c8 split)
#define NREG  2u
#define TREG  (T_SZ / NREG)      // 500,000 texels per region = 32MB

// 32B non-coherent gather
__device__ __forceinline__ void ldg_32B(const void* p, unsigned long long r[4]) {
    asm("ld.global.nc.v4.b64 {%0,%1,%2,%3}, [%4];"
        : "=l"(r[0]), "=l"(r[1]), "=l"(r[2]), "=l"(r[3]) : "l"(p));
}
// 32B streaming store (evict-first: keep output writes out of L2)
__device__ __forceinline__ void stg_cs_32B(void* p, const unsigned long long r[4]) {
    asm volatile("st.global.cs.v4.b64 [%0], {%1,%2,%3,%4};"
                 :: "l"(p), "l"(r[0]), "l"(r[1]), "l"(r[2]), "l"(r[3]) : "memory");
}

// Single-launch region-phased gather, occupancy-tuned.
// blockIdx.y = phase (0..3) = (batch<<1)|region; x-major CTA rasterization
// runs all of phase p before phase p+1, so the gather working set per phase
// is one 32MB texture region (structurally L2-resident; L2 = 126MB).
// Thread layout: i -> c8 = i&1 (which 32B half of the 64B slot), q = i>>1;
// each thread serves 4 slots q + j*QTR. Out-of-region slots are skipped (the
// sibling region phase writes them). Pair-wise load/store keeps only 2x32B
// buffers live; __launch_bounds__(256,6) caps regs so occupancy stays high
// (the R6/R8 failure mode was regs -> occ collapse -> latency-bound).
__global__ __launch_bounds__(256, 6) void gather_phased_kernel(
    const char* __restrict__ tex,    // [B,T,16] f32 (64B per texel row)
    const int*  __restrict__ gidx,   // [G*K]
    char*       __restrict__ out)    // [B,G,K,16] f32 (64B per slot)
{
    const unsigned phase = blockIdx.y;                  // 0..3
    const unsigned tlo   = (phase & 1u) * TREG;         // region lower bound
    const unsigned i     = blockIdx.x * 256u + threadIdx.x;
    if (i >= TPP) return;

    const unsigned c8 = (i & 1u) * 32u;
    const unsigned q  = i >> 1;                         // [0, QTR)

    const char* tb = tex + (size_t)(phase >> 1) * ((size_t)T_SZ * 64u);
    char*       ob = out + (size_t)(phase >> 1) * ((size_t)GK * 64u);

    // 4 coalesced index loads (lane pairs broadcast-share each idx)
    const unsigned t0 = (unsigned)__ldg(&gidx[q]);
    const unsigned t1 = (unsigned)__ldg(&gidx[q +      QTR]);
    const unsigned t2 = (unsigned)__ldg(&gidx[q + 2u * QTR]);
    const unsigned t3 = (unsigned)__ldg(&gidx[q + 3u * QTR]);

    // Pair 1: slots 0,1 — two predicated gathers in flight, then two stores.
    {
        unsigned long long v0[4], v1[4];
        const bool a0 = (t0 - tlo) < TREG;
        const bool a1 = (t1 - tlo) < TREG;
        if (a0) ldg_32B(tb + (size_t)t0 * 64u + c8, v0);
        if (a1) ldg_32B(tb + (size_t)t1 * 64u + c8, v1);
        if (a0) stg_cs_32B(ob + (size_t)q * 64u + c8, v0);
        if (a1) stg_cs_32B(ob + (size_t)(q + QTR) * 64u + c8, v1);
    }
    // Pair 2: slots 2,3
    {
        unsigned long long v2[4], v3[4];
        const bool a2 = (t2 - tlo) < TREG;
        const bool a3 = (t3 - tlo) < TREG;
        if (a2) ldg_32B(tb + (size_t)t2 * 64u + c8, v2);
        if (a3) ldg_32B(tb + (size_t)t3 * 64u + c8, v3);
        if (a2) stg_cs_32B(ob + (size_t)(q + 2u * QTR) * 64u + c8, v2);
        if (a3) stg_cs_32B(ob + (size_t)(q + 3u * QTR) * 64u + c8, v3);
    }
}

extern "C" void kernel_launch(void* const* d_in, const int* in_sizes, int n_in,
                              void* d_out, int out_size) {
    // metadata order: [0] mesh_ids (unused), [1] textures f32 [B,T,C], [2] group_idx i32 [G,K]
    const char* tex  = (const char*)d_in[1];
    const int*  gidx = (const int*)d_in[2];
    char*       out  = (char*)d_out;

    const unsigned bpp = (TPP + 255u) / 256u;   // 8790 blocks per phase
    dim3 grid(bpp, 4u);                          // 4 phases (2 batches x 2 regions)
    gather_phased_kernel<<<grid, 256>>>(tex, gidx, out);
}